// round 12
// baseline (speedup 1.0000x reference)
#include <cuda_runtime.h>
#include <cuda_bf16.h>
#include <cstdint>

#define NVOX   (64*128*128)
#define NB     2
#define NC     32
#define PCAP   2048
#define NCAP   12288
#define COLCAP (PCAP+NCAP)         // 14336
#define MTILE  128                 // anchors per block
#define NTILE  128                 // columns per block
#define NXCH   (PCAP/MTILE)        // 16
#define NYCH   (COLCAP/NTILE)      // 112
#define TOTTK  (NXCH*NYCH*NB)      // 3584 ticket total
#define NROWS  (NB*64*128)         // 16384

typedef unsigned long long ull;

// ---------------- device scratch (no allocations allowed) ----------------
__device__ unsigned g_bfm[NROWS*4];
__device__ unsigned g_bw[NROWS*4];
__device__ int    g_cnt[NB][2];
__device__ int    g_done;
__device__ int    g_posIdx[NB][PCAP];
__device__ int    g_negIdx[NB][NCAP];
// per row: 8 uint4 units; data-unit u stored at slot u^(col&7) (XOR swizzle).
// data units 0-3 = hi bf16x2 words 0-15 (ch 0-31), units 4-7 = lo residual.
__device__ uint4  g_B[NB][COLCAP][8];
__device__ float  g_acc[NB][PCAP][2];     // per-anchor (num, neg)

__device__ __forceinline__ int bidx(int pl, int h, int w) { return pl*512 + h*4 + w; }
__device__ __forceinline__ unsigned packbf(__nv_bfloat16 a, __nv_bfloat16 b) {
    __nv_bfloat162 t; t.x = a; t.y = b;
    return *reinterpret_cast<unsigned*>(&t);
}
__device__ __forceinline__ float ex2f(float x) {
    float r; asm("ex2.approx.ftz.f32 %0, %1;" : "=f"(r) : "f"(x)); return r;
}

// ---------------- stage 1: fg bitmask + W-dilation (fused) ------------------
__global__ void k_pack(const int* __restrict__ lab) {
    int warp = threadIdx.x >> 5, lane = threadIdx.x & 31;
    int row  = blockIdx.x * 8 + warp;
    __shared__ unsigned srow[8][4];
    if (lane < 4) srow[warp][lane] = 0;
    __syncwarp();
    int4 l = *reinterpret_cast<const int4*>(lab + (size_t)row*128 + lane*4);
    unsigned nib = (unsigned)(l.x > 0) | ((unsigned)(l.y > 0) << 1)
                 | ((unsigned)(l.z > 0) << 2) | ((unsigned)(l.w > 0) << 3);
    if (nib) atomicOr(&srow[warp][lane >> 3], nib << ((lane & 7) * 4));
    __syncwarp();
    if (lane < 4) {
        unsigned f  = srow[warp][lane];
        unsigned fl = (lane > 0) ? srow[warp][lane-1] : 0u;
        unsigned fr = (lane < 3) ? srow[warp][lane+1] : 0u;
        unsigned dil = f;
        #pragma unroll
        for (int k = 1; k <= 5; ++k) {
            dil |= __funnelshift_r(f, fr, k);
            dil |= __funnelshift_l(fl, f, k);
        }
        g_bfm[row*4 + lane] = f;
        g_bw[row*4 + lane] = dil;
    }
    if (blockIdx.x < 32) ((float*)g_acc)[blockIdx.x * 256 + threadIdx.x] = 0.f;
    if (blockIdx.x == 0 && threadIdx.x == 0) {
        g_cnt[0][0] = g_cnt[0][1] = g_cnt[1][0] = g_cnt[1][1] = 0;
        g_done = 0;
    }
}

// ---------------- stage 2: fused H+D dilation + rim + atomic emit -----------
// One block per (img, w-word, 4-d-slab): slab of 14 d-planes x 128 h for this
// w-word in smem (H- and D-dilation only ever touch the same w-word, since
// W-dilation was already applied bitwise in k_pack).
__global__ void k_dild() {
    int bx  = blockIdx.x;                 // [0, NB*4*16)
    int img = bx >> 6;
    int w   = (bx >> 4) & 3;
    int d0  = (bx & 15) * 4;
    int tid = threadIdx.x;

    __shared__ unsigned sbw[14*128];
    __shared__ unsigned sbh[14*128];

    #pragma unroll
    for (int i = tid; i < 14*128; i += 256) {
        int dd = d0 - 5 + (i >> 7);
        int h  = i & 127;
        sbw[i] = ((unsigned)dd < 64u) ? g_bw[bidx(img*64 + dd, h, w)] : 0u;
    }
    __syncthreads();
    #pragma unroll
    for (int i = tid; i < 14*128; i += 256) {
        int p = i & ~127;
        int h = i & 127;
        unsigned acc = 0;
        #pragma unroll
        for (int k = -5; k <= 5; ++k) {
            int hh = h + k;
            if ((unsigned)hh < 128u) acc |= sbw[p + hh];
        }
        sbh[i] = acc;
    }
    __syncthreads();
    #pragma unroll
    for (int i = tid; i < 4*128; i += 256) {
        int dr = i >> 7;                  // 0..3
        int d  = d0 + dr;
        int h  = i & 127;
        unsigned acc = 0;
        #pragma unroll
        for (int k = 0; k <= 10; ++k) acc |= sbh[(dr + k)*128 + h];
        unsigned fgw = g_bfm[bidx(img*64 + d, h, w)];
        unsigned rim = acc & ~fgw;
        int vbase = d*16384 + h*128 + w*32;
        if (fgw) {
            int c = __popc(fgw);
            int base = atomicAdd(&g_cnt[img][0], c);
            unsigned m = fgw;
            while (m) {
                int b = __ffs(m) - 1; m &= m - 1;
                if (base < PCAP) g_posIdx[img][base] = vbase + b;
                base++;
            }
        }
        if (rim) {
            int c = __popc(rim);
            int base = atomicAdd(&g_cnt[img][1], c);
            unsigned m = rim;
            while (m) {
                int b = __ffs(m) - 1; m &= m - 1;
                if (base < NCAP) g_negIdx[img][base] = vbase + b;
                base++;
            }
        }
    }
}

// ---------------- stage 3: gather + normalize + bf16 hi/lo split ------------
// 4 threads/row (quads): 8 channel loads each, norm combined with 2 shfl_xor
// (no barriers); each thread writes one hi unit + one lo unit (XOR swizzle).
__global__ void k_gather(const float* __restrict__ feats) {
    int t = blockIdx.x * 256 + threadIdx.x;
    int rsel = t >> 2, q = t & 3;
    int img = rsel / COLCAP;              // < NB by grid construction
    int s = rsel - img * COLCAP;
    int posCnt = min(g_cnt[img][0], PCAP);
    int negCnt = min(g_cnt[img][1], NCAP);
    bool valid; int n = 0, col;
    if (s < PCAP) {
        valid = (s < posCnt);
        n = valid ? g_posIdx[img][s] : 0;
        col = s;
    } else {
        int j = s - PCAP;
        valid = (j < negCnt);
        n = valid ? g_negIdx[img][j] : 0;
        col = posCnt + j;
    }
    const float* f = feats + (size_t)img * NC * NVOX + (size_t)q * 8 * NVOX + n;
    float v[8]; float ss = 0.f;
    #pragma unroll
    for (int k = 0; k < 8; ++k) { v[k] = __ldg(f + (size_t)k * NVOX); ss += v[k]*v[k]; }
    ss += __shfl_xor_sync(0xffffffffu, ss, 1);
    ss += __shfl_xor_sync(0xffffffffu, ss, 2);
    float sc = 1.0f / fmaxf(sqrtf(ss), 1e-12f);

    if (!valid) return;
    unsigned hw[4], lw[4];
    #pragma unroll
    for (int w = 0; w < 4; ++w) {
        float x0 = v[2*w] * sc, x1 = v[2*w+1] * sc;
        __nv_bfloat16 h0 = __float2bfloat16(x0);
        __nv_bfloat16 h1 = __float2bfloat16(x1);
        __nv_bfloat16 l0 = __float2bfloat16(x0 - __bfloat162float(h0));
        __nv_bfloat16 l1 = __float2bfloat16(x1 - __bfloat162float(h1));
        hw[w] = packbf(h0, h1);
        lw[w] = packbf(l0, l1);
    }
    int perm = col & 7;
    uint4* dst = &g_B[img][col][0];
    dst[q       ^ perm] = make_uint4(hw[0], hw[1], hw[2], hw[3]);
    dst[(4 + q) ^ perm] = make_uint4(lw[0], lw[1], lw[2], lw[3]);
}

// ---------------- stage 4: warp-MMA GEMM + epilogue + fused final -----------
// Same proven mma body as R8/R11.  All TOTTK blocks ticket at the end; the
// last block performs the per-image log-loss reduction and writes out[0].
__global__ void __launch_bounds__(256, 2) k_mma(float* out) {
    int img = blockIdx.z;
    int posCnt = min(g_cnt[img][0], PCAP);
    int negCnt = min(g_cnt[img][1], NCAP);
    int nCol = posCnt + negCnt;
    int aBase = blockIdx.x * MTILE;
    int cBase = blockIdx.y * NTILE;
    int t = threadIdx.x;
    bool activeBlk = (aBase < posCnt) && (cBase < nCol);

    __shared__ __align__(16) unsigned sA[MTILE * 32];   // 16 KB
    __shared__ __align__(16) unsigned sB[NTILE * 32];   // 16 KB
    __shared__ int sflag;
    __shared__ float sred[2][256];

    if (activeBlk) {
        {   // linear tile fill (swizzle pre-applied in gmem)
            uint4*       a4 = reinterpret_cast<uint4*>(sA);
            uint4*       b4 = reinterpret_cast<uint4*>(sB);
            const uint4* ga = &g_B[img][aBase][0];
            const uint4* gb = &g_B[img][cBase][0];
            #pragma unroll
            for (int i = 0; i < 4; ++i) {
                a4[t + 256*i] = ga[t + 256*i];
                b4[t + 256*i] = gb[t + 256*i];
            }
        }
        __syncthreads();

        int wid = t >> 5, lane = t & 31;
        int wm = wid & 3, wn = wid >> 2;
        int gq = lane >> 2, tq = lane & 3;
        int rbase = wm * 32, cbw = wn * 64;

        float d[2][8][4];
        #pragma unroll
        for (int mt = 0; mt < 2; ++mt)
            #pragma unroll
            for (int nt = 0; nt < 8; ++nt)
                #pragma unroll
                for (int r = 0; r < 4; ++r) d[mt][nt][r] = 0.f;

        const int awb[6] = {0, 8, 16, 24, 0, 8};
        const int bwb[6] = {0, 8, 0, 8, 16, 24};

        #pragma unroll
        for (int ks = 0; ks < 6; ++ks) {
            int ua = (((awb[ks] >> 2) ^ gq) << 2) + tq;
            int ub = (((bwb[ks] >> 2) ^ gq) << 2) + tq;
            unsigned a[2][4];
            #pragma unroll
            for (int mt = 0; mt < 2; ++mt) {
                int p = (rbase + mt*16 + gq) * 32 + ua;
                a[mt][0] = sA[p];
                a[mt][1] = sA[p + 256];
                a[mt][2] = sA[p ^ 4];
                a[mt][3] = sA[(p + 256) ^ 4];
            }
            #pragma unroll
            for (int nt = 0; nt < 8; ++nt) {
                int p = (cbw + nt*8 + gq) * 32 + ub;
                unsigned b0 = sB[p], b1 = sB[p ^ 4];
                #pragma unroll
                for (int mt = 0; mt < 2; ++mt)
                    asm volatile(
                        "mma.sync.aligned.m16n8k16.row.col.f32.bf16.bf16.f32 "
                        "{%0,%1,%2,%3}, {%4,%5,%6,%7}, {%8,%9}, {%0,%1,%2,%3};"
                        : "+f"(d[mt][nt][0]), "+f"(d[mt][nt][1]),
                          "+f"(d[mt][nt][2]), "+f"(d[mt][nt][3])
                        : "r"(a[mt][0]), "r"(a[mt][1]), "r"(a[mt][2]), "r"(a[mt][3]),
                          "r"(b0), "r"(b1));
            }
        }

        const float SCALE = 14.4269504088896340f;    // (1/TAU) * log2(e)
        #pragma unroll
        for (int mt = 0; mt < 2; ++mt) {
            int r0 = aBase + rbase + mt*16 + gq;
            int r1 = r0 + 8;
            float n0 = 0.f, g0 = 0.f, n1 = 0.f, g1 = 0.f;
            #pragma unroll
            for (int nt = 0; nt < 8; ++nt) {
                int c = cBase + cbw + nt*8 + 2*tq;
                #pragma unroll
                for (int r = 0; r < 4; ++r) {
                    int cg = c + (r & 1);
                    int rg = (r < 2) ? r0 : r1;
                    if (cg < nCol) {
                        float e = ex2f(d[mt][nt][r] * SCALE);
                        if (cg < posCnt) {
                            if (cg != rg) { if (r < 2) n0 += e; else n1 += e; }
                        } else { if (r < 2) g0 += e; else g1 += e; }
                    }
                }
            }
            #pragma unroll
            for (int off = 1; off <= 2; off <<= 1) {
                n0 += __shfl_xor_sync(0xffffffffu, n0, off);
                g0 += __shfl_xor_sync(0xffffffffu, g0, off);
                n1 += __shfl_xor_sync(0xffffffffu, n1, off);
                g1 += __shfl_xor_sync(0xffffffffu, g1, off);
            }
            if (tq == 0) {
                if (r0 < posCnt) { atomicAdd(&g_acc[img][r0][0], n0); atomicAdd(&g_acc[img][r0][1], g0); }
                if (r1 < posCnt) { atomicAdd(&g_acc[img][r1][0], n1); atomicAdd(&g_acc[img][r1][1], g1); }
            }
        }
        __threadfence();                  // make this thread's REDs visible
    }

    // ---- ticket: last of all TOTTK blocks reduces and writes the output ----
    __syncthreads();
    if (t == 0) {
        int tk = atomicAdd(&g_done, 1);
        sflag = (tk == TOTTK - 1);
    }
    __syncthreads();
    if (!sflag) return;
    __threadfence();

    float loss[NB]; int vld[NB];
    for (int im = 0; im < NB; ++im) {
        int pc  = min(g_cnt[im][0], PCAP);
        int ngc = min(g_cnt[im][1], NCAP);
        float sum = 0.f, cnt = 0.f;
        for (int a = t; a < pc; a += 256) {
            float num = __ldcg(&g_acc[im][a][0]);
            float neg = __ldcg(&g_acc[im][a][1]);
            if (num > 0.f) { sum += log1pf(neg / num); cnt += 1.f; }
        }
        sred[0][t] = sum; sred[1][t] = cnt;
        __syncthreads();
        for (int o = 128; o > 0; o >>= 1) {
            if (t < o) { sred[0][t] += sred[0][t + o]; sred[1][t] += sred[1][t + o]; }
            __syncthreads();
        }
        loss[im] = sred[0][0] / fmaxf(sred[1][0], 1.f);
        vld[im]  = (pc >= 2 && ngc > 0 && sred[1][0] > 0.f) ? 1 : 0;
        __syncthreads();
    }
    if (t == 0) {
        float v0 = vld[0] ? 1.f : 0.f;
        float v1 = vld[1] ? 1.f : 0.f;
        float s = loss[0]*v0 + loss[1]*v1;
        float tot = s / fmaxf(v0 + v1, 1.f);
        out[0] = (v0 + v1 > 0.f) ? tot : 0.f;
    }
}

// ---------------- launch ----------------
extern "C" void kernel_launch(void* const* d_in, const int* in_sizes, int n_in,
                              void* d_out, int out_size) {
    const float* feats = (const float*)d_in[0];
    const int*   lab   = (const int*)d_in[1];
    (void)in_sizes; (void)n_in; (void)out_size;

    k_pack  <<<NROWS/8, 256>>>(lab);
    k_dild  <<<NB*4*16, 256>>>();
    k_gather<<<NB*COLCAP*4/256, 256>>>(feats);
    k_mma   <<<dim3(NXCH, NYCH, NB), 256>>>((float*)d_out);
}

// round 14
// speedup vs baseline: 1.8254x; 1.8254x over previous
#include <cuda_runtime.h>
#include <cuda_fp16.h>
#include <cstdint>

#define NVOX   (64*128*128)
#define NB     2
#define NC     32
#define PCAP   2048
#define NCAP   12288
#define COLCAP (PCAP+NCAP)         // 14336
#define MTILE  128                 // anchors per block
#define NTILE  128                 // columns per block
#define NXCH   (PCAP/MTILE)        // 16
#define NYCH   (COLCAP/NTILE)      // 112
#define NROWS  (NB*64*128)         // 16384

typedef unsigned long long ull;

// ---------------- device scratch (no allocations allowed) ----------------
__device__ unsigned g_bfm[NROWS*4];
__device__ unsigned g_bw[NROWS*4];
__device__ int    g_cnt[NB][2];
__device__ int    g_done;
__device__ int    g_posIdx[NB][PCAP];
__device__ int    g_negIdx[NB][NCAP];
// per row: 8 uint4 units; data-unit u stored at slot u^(col&7) (XOR swizzle).
// data units 0-3 = hi fp16x2 words 0-15 (ch 0-31), units 4-7 = lo residual.
__device__ uint4  g_B[NB][COLCAP][8];
__device__ float  g_acc[NB][PCAP][2];     // per-anchor (num, neg)
__device__ float  g_imgLoss[NB];
__device__ int    g_imgValid[NB];

__device__ __forceinline__ int bidx(int pl, int h, int w) { return pl*512 + h*4 + w; }
__device__ __forceinline__ unsigned packh(__half a, __half b) {
    __half2 t = __halves2half2(a, b);
    return *reinterpret_cast<unsigned*>(&t);
}
__device__ __forceinline__ float ex2f(float x) {
    float r; asm("ex2.approx.ftz.f32 %0, %1;" : "=f"(r) : "f"(x)); return r;
}

// ---------------- stage 1: fg bitmask + W-dilation (fused) ------------------
__global__ void k_pack(const int* __restrict__ lab) {
    int warp = threadIdx.x >> 5, lane = threadIdx.x & 31;
    int row  = blockIdx.x * 8 + warp;
    __shared__ unsigned srow[8][4];
    if (lane < 4) srow[warp][lane] = 0;
    __syncwarp();
    int4 l = *reinterpret_cast<const int4*>(lab + (size_t)row*128 + lane*4);
    unsigned nib = (unsigned)(l.x > 0) | ((unsigned)(l.y > 0) << 1)
                 | ((unsigned)(l.z > 0) << 2) | ((unsigned)(l.w > 0) << 3);
    if (nib) atomicOr(&srow[warp][lane >> 3], nib << ((lane & 7) * 4));
    __syncwarp();
    if (lane < 4) {
        unsigned f  = srow[warp][lane];
        unsigned fl = (lane > 0) ? srow[warp][lane-1] : 0u;
        unsigned fr = (lane < 3) ? srow[warp][lane+1] : 0u;
        unsigned dil = f;
        #pragma unroll
        for (int k = 1; k <= 5; ++k) {
            dil |= __funnelshift_r(f, fr, k);
            dil |= __funnelshift_l(fl, f, k);
        }
        g_bfm[row*4 + lane] = f;
        g_bw[row*4 + lane] = dil;
    }
    if (blockIdx.x < 32) ((float*)g_acc)[blockIdx.x * 256 + threadIdx.x] = 0.f;
    if (blockIdx.x == 0 && threadIdx.x == 0) {
        g_cnt[0][0] = g_cnt[0][1] = g_cnt[1][0] = g_cnt[1][1] = 0;
        g_done = 0;
    }
}

// ---------------- stage 2: fused H+D dilation + rim + atomic emit -----------
__global__ void k_dild() {
    int bx  = blockIdx.x;                 // [0, NB*4*16)
    int img = bx >> 6;
    int w   = (bx >> 4) & 3;
    int d0  = (bx & 15) * 4;
    int tid = threadIdx.x;

    __shared__ unsigned sbw[14*128];
    __shared__ unsigned sbh[14*128];

    #pragma unroll
    for (int i = tid; i < 14*128; i += 256) {
        int dd = d0 - 5 + (i >> 7);
        int h  = i & 127;
        sbw[i] = ((unsigned)dd < 64u) ? g_bw[bidx(img*64 + dd, h, w)] : 0u;
    }
    __syncthreads();
    #pragma unroll
    for (int i = tid; i < 14*128; i += 256) {
        int p = i & ~127;
        int h = i & 127;
        unsigned acc = 0;
        #pragma unroll
        for (int k = -5; k <= 5; ++k) {
            int hh = h + k;
            if ((unsigned)hh < 128u) acc |= sbw[p + hh];
        }
        sbh[i] = acc;
    }
    __syncthreads();
    #pragma unroll
    for (int i = tid; i < 4*128; i += 256) {
        int dr = i >> 7;
        int d  = d0 + dr;
        int h  = i & 127;
        unsigned acc = 0;
        #pragma unroll
        for (int k = 0; k <= 10; ++k) acc |= sbh[(dr + k)*128 + h];
        unsigned fgw = g_bfm[bidx(img*64 + d, h, w)];
        unsigned rim = acc & ~fgw;
        int vbase = d*16384 + h*128 + w*32;
        if (fgw) {
            int c = __popc(fgw);
            int base = atomicAdd(&g_cnt[img][0], c);
            unsigned m = fgw;
            while (m) {
                int b = __ffs(m) - 1; m &= m - 1;
                if (base < PCAP) g_posIdx[img][base] = vbase + b;
                base++;
            }
        }
        if (rim) {
            int c = __popc(rim);
            int base = atomicAdd(&g_cnt[img][1], c);
            unsigned m = rim;
            while (m) {
                int b = __ffs(m) - 1; m &= m - 1;
                if (base < NCAP) g_negIdx[img][base] = vbase + b;
                base++;
            }
        }
    }
}

// ---------------- stage 3: gather + normalize + fp16 hi/lo split ------------
// 4 threads/row (quads): 8 channel loads each, norm via 2 shfl_xor.
__global__ void k_gather(const float* __restrict__ feats) {
    int t = blockIdx.x * 256 + threadIdx.x;
    int rsel = t >> 2, q = t & 3;
    int img = rsel / COLCAP;
    int s = rsel - img * COLCAP;
    int posCnt = min(g_cnt[img][0], PCAP);
    int negCnt = min(g_cnt[img][1], NCAP);
    bool valid; int n = 0, col;
    if (s < PCAP) {
        valid = (s < posCnt);
        n = valid ? g_posIdx[img][s] : 0;
        col = s;
    } else {
        int j = s - PCAP;
        valid = (j < negCnt);
        n = valid ? g_negIdx[img][j] : 0;
        col = posCnt + j;
    }
    const float* f = feats + (size_t)img * NC * NVOX + (size_t)q * 8 * NVOX + n;
    float v[8]; float ss = 0.f;
    #pragma unroll
    for (int k = 0; k < 8; ++k) { v[k] = __ldg(f + (size_t)k * NVOX); ss += v[k]*v[k]; }
    ss += __shfl_xor_sync(0xffffffffu, ss, 1);
    ss += __shfl_xor_sync(0xffffffffu, ss, 2);
    float sc = 1.0f / fmaxf(sqrtf(ss), 1e-12f);

    if (!valid) return;
    unsigned hw[4], lw[4];
    #pragma unroll
    for (int w = 0; w < 4; ++w) {
        float x0 = v[2*w] * sc, x1 = v[2*w+1] * sc;
        __half h0 = __float2half(x0);
        __half h1 = __float2half(x1);
        __half l0 = __float2half(x0 - __half2float(h0));
        __half l1 = __float2half(x1 - __half2float(h1));
        hw[w] = packh(h0, h1);
        lw[w] = packh(l0, l1);
    }
    int perm = col & 7;
    uint4* dst = &g_B[img][col][0];
    dst[q       ^ perm] = make_uint4(hw[0], hw[1], hw[2], hw[3]);
    dst[(4 + q) ^ perm] = make_uint4(lw[0], lw[1], lw[2], lw[3]);
}

// ---------------- stage 4: warp-MMA fp16 2-term GEMM + softmax epilogue -----
// Block: 128x128, 8 warps (wm=wid&3: 32 rows, wn=wid>>2: 64 cols).
// 4 k-steps: (ah,bh)(0-15ch),(ah,bh)(16-31),(al,bh)(0-15),(al,bh)(16-31)
//   = (ah+al)*bh = a*bh exactly in fp32 accum; only B-side fp16 rounding
//   remains (|db| <= 2^-12).  B tile: only hi data-units copied (slots
//   preserved under XOR swizzle, so fragment addressing is unchanged).
__global__ void __launch_bounds__(256, 2) k_mma() {
    int img = blockIdx.z;
    int posCnt = min(g_cnt[img][0], PCAP);
    int negCnt = min(g_cnt[img][1], NCAP);
    int nCol = posCnt + negCnt;
    int aBase = blockIdx.x * MTILE;
    int cBase = blockIdx.y * NTILE;
    if (aBase >= posCnt || cBase >= nCol) return;

    __shared__ __align__(16) unsigned sA[MTILE * 32];   // 16 KB (hi+lo)
    __shared__ __align__(16) unsigned sB[NTILE * 32];   // 16 KB (hi slots only filled)

    int t = threadIdx.x;
    {
        uint4*       a4 = reinterpret_cast<uint4*>(sA);
        uint4*       b4 = reinterpret_cast<uint4*>(sB);
        const uint4* ga = &g_B[img][aBase][0];
        const uint4* gb = &g_B[img][cBase][0];
        #pragma unroll
        for (int i = 0; i < 4; ++i)                 // full A tile (1024 uint4)
            a4[t + 256*i] = ga[t + 256*i];
        #pragma unroll
        for (int i = 0; i < 2; ++i) {               // hi half of B tile (512 uint4)
            int idx = t + 256*i;                    // idx = col*4 + u, u = data-unit 0..3
            int col = idx >> 2, u = idx & 3;
            int slot = u ^ (col & 7);
            b4[col*8 + slot] = gb[col*8 + slot];
        }
    }
    __syncthreads();

    int wid = t >> 5, lane = t & 31;
    int wm = wid & 3, wn = wid >> 2;
    int gq = lane >> 2, tq = lane & 3;
    int rbase = wm * 32, cbw = wn * 64;

    float d[2][8][4];
    #pragma unroll
    for (int mt = 0; mt < 2; ++mt)
        #pragma unroll
        for (int nt = 0; nt < 8; ++nt)
            #pragma unroll
            for (int r = 0; r < 4; ++r) d[mt][nt][r] = 0.f;

    const int awb[4] = {0, 8, 16, 24};   // A: hi,hi,lo,lo
    const int bwb[4] = {0, 8, 0, 8};     // B: hi words only

    #pragma unroll
    for (int ks = 0; ks < 4; ++ks) {
        int ua = (((awb[ks] >> 2) ^ gq) << 2) + tq;
        int ub = (((bwb[ks] >> 2) ^ gq) << 2) + tq;
        unsigned a[2][4];
        #pragma unroll
        for (int mt = 0; mt < 2; ++mt) {
            int p = (rbase + mt*16 + gq) * 32 + ua;
            a[mt][0] = sA[p];
            a[mt][1] = sA[p + 256];
            a[mt][2] = sA[p ^ 4];
            a[mt][3] = sA[(p + 256) ^ 4];
        }
        #pragma unroll
        for (int nt = 0; nt < 8; ++nt) {
            int p = (cbw + nt*8 + gq) * 32 + ub;
            unsigned b0 = sB[p], b1 = sB[p ^ 4];
            #pragma unroll
            for (int mt = 0; mt < 2; ++mt)
                asm volatile(
                    "mma.sync.aligned.m16n8k16.row.col.f32.f16.f16.f32 "
                    "{%0,%1,%2,%3}, {%4,%5,%6,%7}, {%8,%9}, {%0,%1,%2,%3};"
                    : "+f"(d[mt][nt][0]), "+f"(d[mt][nt][1]),
                      "+f"(d[mt][nt][2]), "+f"(d[mt][nt][3])
                    : "r"(a[mt][0]), "r"(a[mt][1]), "r"(a[mt][2]), "r"(a[mt][3]),
                      "r"(b0), "r"(b1));
        }
    }

    const float SCALE = 14.4269504088896340f;    // (1/TAU) * log2(e)
    #pragma unroll
    for (int mt = 0; mt < 2; ++mt) {
        int r0 = aBase + rbase + mt*16 + gq;
        int r1 = r0 + 8;
        float n0 = 0.f, g0 = 0.f, n1 = 0.f, g1 = 0.f;
        #pragma unroll
        for (int nt = 0; nt < 8; ++nt) {
            int c = cBase + cbw + nt*8 + 2*tq;
            #pragma unroll
            for (int r = 0; r < 4; ++r) {
                int cg = c + (r & 1);
                int rg = (r < 2) ? r0 : r1;
                if (cg < nCol) {
                    float e = ex2f(d[mt][nt][r] * SCALE);
                    if (cg < posCnt) {
                        if (cg != rg) { if (r < 2) n0 += e; else n1 += e; }
                    } else { if (r < 2) g0 += e; else g1 += e; }
                }
            }
        }
        #pragma unroll
        for (int off = 1; off <= 2; off <<= 1) {
            n0 += __shfl_xor_sync(0xffffffffu, n0, off);
            g0 += __shfl_xor_sync(0xffffffffu, g0, off);
            n1 += __shfl_xor_sync(0xffffffffu, n1, off);
            g1 += __shfl_xor_sync(0xffffffffu, g1, off);
        }
        if (tq == 0) {
            if (r0 < posCnt) { atomicAdd(&g_acc[img][r0][0], n0); atomicAdd(&g_acc[img][r0][1], g0); }
            if (r1 < posCnt) { atomicAdd(&g_acc[img][r1][0], n1); atomicAdd(&g_acc[img][r1][1], g1); }
        }
    }
}

// ---------------- stage 5: per-image reduction + final (ticketed) -----------
__global__ void k_redfinal(float* out) {
    int img = blockIdx.x;
    int tid = threadIdx.x;
    int posCnt = min(g_cnt[img][0], PCAP);
    int negCnt = min(g_cnt[img][1], NCAP);
    float sum = 0.f, cnt = 0.f;
    for (int a = tid; a < posCnt; a += 256) {
        float num = g_acc[img][a][0];
        float neg = g_acc[img][a][1];
        if (num > 0.f) { sum += log1pf(neg / num); cnt += 1.f; }
    }
    __shared__ float ss[256], sc[256];
    ss[tid] = sum; sc[tid] = cnt;
    __syncthreads();
    for (int o = 128; o > 0; o >>= 1) {
        if (tid < o) { ss[tid] += ss[tid + o]; sc[tid] += sc[tid + o]; }
        __syncthreads();
    }
    if (tid == 0) {
        g_imgLoss[img]  = ss[0] / fmaxf(sc[0], 1.f);
        g_imgValid[img] = (posCnt >= 2 && negCnt > 0 && sc[0] > 0.f) ? 1 : 0;
        __threadfence();
        int ticket = atomicAdd(&g_done, 1);
        if (ticket == NB - 1) {
            float v0 = g_imgValid[0] ? 1.f : 0.f;
            float v1 = g_imgValid[1] ? 1.f : 0.f;
            float s = g_imgLoss[0]*v0 + g_imgLoss[1]*v1;
            float tot = s / fmaxf(v0 + v1, 1.f);
            out[0] = (v0 + v1 > 0.f) ? tot : 0.f;
        }
    }
}

// ---------------- launch ----------------
extern "C" void kernel_launch(void* const* d_in, const int* in_sizes, int n_in,
                              void* d_out, int out_size) {
    const float* feats = (const float*)d_in[0];
    const int*   lab   = (const int*)d_in[1];
    (void)in_sizes; (void)n_in; (void)out_size;

    k_pack  <<<NROWS/8, 256>>>(lab);
    k_dild  <<<NB*4*16, 256>>>();
    k_gather<<<NB*COLCAP*4/256, 256>>>(feats);
    k_mma   <<<dim3(NXCH, NYCH, NB), 256>>>();
    k_redfinal<<<NB, 256>>>((float*)d_out);
}

// round 17
// speedup vs baseline: 2.1725x; 1.1902x over previous
#include <cuda_runtime.h>
#include <cuda_fp16.h>
#include <cstdint>

#define NVOX   (64*128*128)
#define NB     2
#define NC     32
#define PCAP   2048
#define NCAP   12288
#define COLCAP (PCAP+NCAP)         // 14336
#define MTILE  128                 // anchors per block
#define NTILE  128                 // columns per block
#define NXCH   (PCAP/MTILE)        // 16
#define NYCH   (COLCAP/NTILE)      // 112
#define NROWS  (NB*64*128)         // 16384

typedef unsigned long long ull;

// ---------------- device scratch (no allocations allowed) ----------------
__device__ unsigned g_bfm[NROWS*4];
__device__ unsigned g_bw[NROWS*4];
__device__ int    g_cnt[NB][2];
__device__ int    g_done;
__device__ int    g_posIdx[NB][PCAP];
__device__ int    g_negIdx[NB][NCAP];
// per row: 8 uint4 units; data-unit u stored at slot u^(col&7) (XOR swizzle).
// g_B: units 0-3 = UNscaled hi fp16x2 words 0-15 (ch 0-31), 4-7 = lo residual.
// g_A: same layout but values pre-scaled by (1/TAU)*log2(e)  (pos rows only).
__device__ uint4  g_B[NB][COLCAP][8];
__device__ uint4  g_A[NB][PCAP][8];
__device__ float  g_acc[NB][PCAP][2];     // per-anchor (num, neg)
__device__ float  g_imgLoss[NB];
__device__ int    g_imgValid[NB];

__device__ __forceinline__ int bidx(int pl, int h, int w) { return pl*512 + h*4 + w; }
__device__ __forceinline__ unsigned packh(__half a, __half b) {
    __half2 t = __halves2half2(a, b);
    return *reinterpret_cast<unsigned*>(&t);
}
__device__ __forceinline__ float ex2f(float x) {
    float r; asm("ex2.approx.ftz.f32 %0, %1;" : "=f"(r) : "f"(x)); return r;
}
__device__ __forceinline__ uint32_t smem_u32(const void* p) {
    uint32_t a;
    asm("{ .reg .u64 t; cvta.to.shared.u64 t, %1; cvt.u32.u64 %0, t; }" : "=r"(a) : "l"(p));
    return a;
}
#define LDMATRIX_X4(r0, r1, r2, r3, addr) \
    asm volatile("ldmatrix.sync.aligned.m8n8.x4.shared.b16 {%0,%1,%2,%3}, [%4];" \
        : "=r"(r0), "=r"(r1), "=r"(r2), "=r"(r3) : "r"(addr))

// ---------------- stage 1: fg bitmask + W-dilation (fused) ------------------
__global__ void k_pack(const int* __restrict__ lab) {
    int warp = threadIdx.x >> 5, lane = threadIdx.x & 31;
    int row  = blockIdx.x * 8 + warp;
    __shared__ unsigned srow[8][4];
    if (lane < 4) srow[warp][lane] = 0;
    __syncwarp();
    int4 l = *reinterpret_cast<const int4*>(lab + (size_t)row*128 + lane*4);
    unsigned nib = (unsigned)(l.x > 0) | ((unsigned)(l.y > 0) << 1)
                 | ((unsigned)(l.z > 0) << 2) | ((unsigned)(l.w > 0) << 3);
    if (nib) atomicOr(&srow[warp][lane >> 3], nib << ((lane & 7) * 4));
    __syncwarp();
    if (lane < 4) {
        unsigned f  = srow[warp][lane];
        unsigned fl = (lane > 0) ? srow[warp][lane-1] : 0u;
        unsigned fr = (lane < 3) ? srow[warp][lane+1] : 0u;
        unsigned dil = f;
        #pragma unroll
        for (int k = 1; k <= 5; ++k) {
            dil |= __funnelshift_r(f, fr, k);
            dil |= __funnelshift_l(fl, f, k);
        }
        g_bfm[row*4 + lane] = f;
        g_bw[row*4 + lane] = dil;
    }
    if (blockIdx.x < 32) ((float*)g_acc)[blockIdx.x * 256 + threadIdx.x] = 0.f;
    if (blockIdx.x == 0 && threadIdx.x == 0) {
        g_cnt[0][0] = g_cnt[0][1] = g_cnt[1][0] = g_cnt[1][1] = 0;
        g_done = 0;
    }
}

// ---------------- stage 2: fused H+D dilation + rim + atomic emit -----------
__global__ void k_dild() {
    int bx  = blockIdx.x;                 // [0, NB*4*16)
    int img = bx >> 6;
    int w   = (bx >> 4) & 3;
    int d0  = (bx & 15) * 4;
    int tid = threadIdx.x;

    __shared__ unsigned sbw[14*128];
    __shared__ unsigned sbh[14*128];

    #pragma unroll
    for (int i = tid; i < 14*128; i += 256) {
        int dd = d0 - 5 + (i >> 7);
        int h  = i & 127;
        sbw[i] = ((unsigned)dd < 64u) ? g_bw[bidx(img*64 + dd, h, w)] : 0u;
    }
    __syncthreads();
    #pragma unroll
    for (int i = tid; i < 14*128; i += 256) {
        int p = i & ~127;
        int h = i & 127;
        unsigned acc = 0;
        #pragma unroll
        for (int k = -5; k <= 5; ++k) {
            int hh = h + k;
            if ((unsigned)hh < 128u) acc |= sbw[p + hh];
        }
        sbh[i] = acc;
    }
    __syncthreads();
    #pragma unroll
    for (int i = tid; i < 4*128; i += 256) {
        int dr = i >> 7;
        int d  = d0 + dr;
        int h  = i & 127;
        unsigned acc = 0;
        #pragma unroll
        for (int k = 0; k <= 10; ++k) acc |= sbh[(dr + k)*128 + h];
        unsigned fgw = g_bfm[bidx(img*64 + d, h, w)];
        unsigned rim = acc & ~fgw;
        int vbase = d*16384 + h*128 + w*32;
        if (fgw) {
            int c = __popc(fgw);
            int base = atomicAdd(&g_cnt[img][0], c);
            unsigned m = fgw;
            while (m) {
                int b = __ffs(m) - 1; m &= m - 1;
                if (base < PCAP) g_posIdx[img][base] = vbase + b;
                base++;
            }
        }
        if (rim) {
            int c = __popc(rim);
            int base = atomicAdd(&g_cnt[img][1], c);
            unsigned m = rim;
            while (m) {
                int b = __ffs(m) - 1; m &= m - 1;
                if (base < NCAP) g_negIdx[img][base] = vbase + b;
                base++;
            }
        }
    }
}

// ---------------- stage 3: gather + normalize + fp16 hi/lo split ------------
// 4 threads/row (quads): 8 channel loads each, norm via 2 shfl_xor.
// All rows -> g_B (unscaled); pos rows additionally -> g_A (pre-scaled).
__global__ void k_gather(const float* __restrict__ feats) {
    const float SCALE = 14.4269504088896340f;    // (1/TAU) * log2(e)
    int t = blockIdx.x * 256 + threadIdx.x;
    int rsel = t >> 2, q = t & 3;
    int img = rsel / COLCAP;
    int s = rsel - img * COLCAP;
    int posCnt = min(g_cnt[img][0], PCAP);
    int negCnt = min(g_cnt[img][1], NCAP);
    bool valid, isPos; int n = 0, col;
    if (s < PCAP) {
        valid = (s < posCnt); isPos = true;
        n = valid ? g_posIdx[img][s] : 0;
        col = s;
    } else {
        int j = s - PCAP;
        valid = (j < negCnt); isPos = false;
        n = valid ? g_negIdx[img][j] : 0;
        col = posCnt + j;
    }
    const float* f = feats + (size_t)img * NC * NVOX + (size_t)q * 8 * NVOX + n;
    float v[8]; float ss = 0.f;
    #pragma unroll
    for (int k = 0; k < 8; ++k) { v[k] = __ldg(f + (size_t)k * NVOX); ss += v[k]*v[k]; }
    ss += __shfl_xor_sync(0xffffffffu, ss, 1);
    ss += __shfl_xor_sync(0xffffffffu, ss, 2);
    float sc = 1.0f / fmaxf(sqrtf(ss), 1e-12f);

    if (!valid) return;
    int perm = col & 7;
    {
        unsigned hw[4], lw[4];
        #pragma unroll
        for (int w = 0; w < 4; ++w) {
            float x0 = v[2*w] * sc, x1 = v[2*w+1] * sc;
            __half h0 = __float2half(x0);
            __half h1 = __float2half(x1);
            __half l0 = __float2half(x0 - __half2float(h0));
            __half l1 = __float2half(x1 - __half2float(h1));
            hw[w] = packh(h0, h1);
            lw[w] = packh(l0, l1);
        }
        uint4* dst = &g_B[img][col][0];
        dst[q       ^ perm] = make_uint4(hw[0], hw[1], hw[2], hw[3]);
        dst[(4 + q) ^ perm] = make_uint4(lw[0], lw[1], lw[2], lw[3]);
    }
    if (isPos) {                                 // scaled copy for the A side
        unsigned hw[4], lw[4];
        #pragma unroll
        for (int w = 0; w < 4; ++w) {
            float x0 = v[2*w] * sc * SCALE, x1 = v[2*w+1] * sc * SCALE;
            __half h0 = __float2half(x0);
            __half h1 = __float2half(x1);
            __half l0 = __float2half(x0 - __half2float(h0));
            __half l1 = __float2half(x1 - __half2float(h1));
            hw[w] = packh(h0, h1);
            lw[w] = packh(l0, l1);
        }
        uint4* dst = &g_A[img][s][0];
        dst[q       ^ perm] = make_uint4(hw[0], hw[1], hw[2], hw[3]);
        dst[(4 + q) ^ perm] = make_uint4(lw[0], lw[1], lw[2], lw[3]);
    }
}

// ---------------- stage 4: warp-MMA fp16 GEMM (ldmatrix) + epilogue ---------
// Block 128x128, 8 warps (wm=wid&3: 32 rows, wn=wid>>2: 64 cols).
// A from g_A (pre-scaled, hi+lo), B from g_B (hi only): 4 k-steps of
// (ah|al)*bh = a*bh exact in fp32 accum.  Fragments via ldmatrix.x4 over the
// XOR-swizzled tiles; per-k-step address = base XOR (unit<<4).
// D is already in exp2 units; pure-neg full tiles take a branch-free epilogue.
__global__ void __launch_bounds__(256, 2) k_mma() {
    int img = blockIdx.z;
    int posCnt = min(g_cnt[img][0], PCAP);
    int negCnt = min(g_cnt[img][1], NCAP);
    int nCol = posCnt + negCnt;
    int aBase = blockIdx.x * MTILE;
    int cBase = blockIdx.y * NTILE;
    if (aBase >= posCnt || cBase >= nCol) return;

    __shared__ __align__(16) unsigned sA[MTILE * 32];   // 16 KB (hi+lo, scaled)
    __shared__ __align__(16) unsigned sB[NTILE * 32];   // 16 KB (hi slots filled)

    int t = threadIdx.x;
    {
        uint4*       a4 = reinterpret_cast<uint4*>(sA);
        uint4*       b4 = reinterpret_cast<uint4*>(sB);
        const uint4* ga = &g_A[img][aBase][0];
        const uint4* gb = &g_B[img][cBase][0];
        #pragma unroll
        for (int i = 0; i < 4; ++i)                 // full A tile
            a4[t + 256*i] = ga[t + 256*i];
        #pragma unroll
        for (int i = 0; i < 2; ++i) {               // hi half of B tile
            int idx = t + 256*i;                    // col*4 + dataunit
            int col = idx >> 2, u = idx & 3;
            int slot = u ^ (col & 7);
            b4[col*8 + slot] = gb[col*8 + slot];
        }
    }
    __syncthreads();

    int wid = t >> 5, lane = t & 31;
    int wm = wid & 3, wn = wid >> 2;
    int gq = lane >> 2, tq = lane & 3;
    int rbase = wm * 32, cbw = wn * 64;
    int l7 = lane & 7, lhi = (lane >> 3) & 1, lx = lane >> 4;

    // ldmatrix lane addresses (byte, shared space)
    uint32_t baseA = smem_u32(sA), baseB = smem_u32(sB);
    uint32_t adA[2], adB[4];
    #pragma unroll
    for (int mt = 0; mt < 2; ++mt) {
        int row = rbase + mt*16 + l7 + 8*lhi;
        adA[mt] = baseA + row*128 + (((lx ^ (row & 7)) & 7) << 4);
    }
    #pragma unroll
    for (int p = 0; p < 4; ++p) {
        int col = cbw + p*16 + l7 + 8*lx;
        adB[p] = baseB + col*128 + (((lhi ^ (col & 7)) & 7) << 4);
    }

    float d[2][8][4];
    #pragma unroll
    for (int mt = 0; mt < 2; ++mt)
        #pragma unroll
        for (int nt = 0; nt < 8; ++nt)
            #pragma unroll
            for (int r = 0; r < 4; ++r) d[mt][nt][r] = 0.f;

    const int aux[4] = {0, 2, 4, 6};     // A unit base per ks (hi,hi,lo,lo)
    const int bux[4] = {0, 2, 0, 2};     // B unit base per ks (hi words only)

    #pragma unroll
    for (int ks = 0; ks < 4; ++ks) {
        unsigned a[2][4];
        #pragma unroll
        for (int mt = 0; mt < 2; ++mt)
            LDMATRIX_X4(a[mt][0], a[mt][1], a[mt][2], a[mt][3],
                        adA[mt] ^ (aux[ks] << 4));
        #pragma unroll
        for (int p = 0; p < 4; ++p) {
            unsigned b0, b1, b2, b3;     // b0,b1 for nt=2p; b2,b3 for nt=2p+1
            LDMATRIX_X4(b0, b1, b2, b3, adB[p] ^ (bux[ks] << 4));
            #pragma unroll
            for (int mt = 0; mt < 2; ++mt) {
                asm volatile(
                    "mma.sync.aligned.m16n8k16.row.col.f32.f16.f16.f32 "
                    "{%0,%1,%2,%3}, {%4,%5,%6,%7}, {%8,%9}, {%0,%1,%2,%3};"
                    : "+f"(d[mt][2*p][0]), "+f"(d[mt][2*p][1]),
                      "+f"(d[mt][2*p][2]), "+f"(d[mt][2*p][3])
                    : "r"(a[mt][0]), "r"(a[mt][1]), "r"(a[mt][2]), "r"(a[mt][3]),
                      "r"(b0), "r"(b1));
                asm volatile(
                    "mma.sync.aligned.m16n8k16.row.col.f32.f16.f16.f32 "
                    "{%0,%1,%2,%3}, {%4,%5,%6,%7}, {%8,%9}, {%0,%1,%2,%3};"
                    : "+f"(d[mt][2*p+1][0]), "+f"(d[mt][2*p+1][1]),
                      "+f"(d[mt][2*p+1][2]), "+f"(d[mt][2*p+1][3])
                    : "r"(a[mt][0]), "r"(a[mt][1]), "r"(a[mt][2]), "r"(a[mt][3]),
                      "r"(b2), "r"(b3));
            }
        }
    }

    bool pureNeg = (cBase >= posCnt) && (cBase + NTILE <= nCol);
    if (pureNeg) {
        #pragma unroll
        for (int mt = 0; mt < 2; ++mt) {
            int r0 = aBase + rbase + mt*16 + gq;
            int r1 = r0 + 8;
            float g0 = 0.f, g1 = 0.f;
            #pragma unroll
            for (int nt = 0; nt < 8; ++nt) {
                g0 += ex2f(d[mt][nt][0]); g0 += ex2f(d[mt][nt][1]);
                g1 += ex2f(d[mt][nt][2]); g1 += ex2f(d[mt][nt][3]);
            }
            #pragma unroll
            for (int off = 1; off <= 2; off <<= 1) {
                g0 += __shfl_xor_sync(0xffffffffu, g0, off);
                g1 += __shfl_xor_sync(0xffffffffu, g1, off);
            }
            if (tq == 0) {
                if (r0 < posCnt) atomicAdd(&g_acc[img][r0][1], g0);
                if (r1 < posCnt) atomicAdd(&g_acc[img][r1][1], g1);
            }
        }
    } else {
        #pragma unroll
        for (int mt = 0; mt < 2; ++mt) {
            int r0 = aBase + rbase + mt*16 + gq;
            int r1 = r0 + 8;
            float n0 = 0.f, g0 = 0.f, n1 = 0.f, g1 = 0.f;
            #pragma unroll
            for (int nt = 0; nt < 8; ++nt) {
                int c = cBase + cbw + nt*8 + 2*tq;
                #pragma unroll
                for (int r = 0; r < 4; ++r) {
                    int cg = c + (r & 1);
                    int rg = (r < 2) ? r0 : r1;
                    if (cg < nCol) {
                        float e = ex2f(d[mt][nt][r]);
                        if (cg < posCnt) {
                            if (cg != rg) { if (r < 2) n0 += e; else n1 += e; }
                        } else { if (r < 2) g0 += e; else g1 += e; }
                    }
                }
            }
            #pragma unroll
            for (int off = 1; off <= 2; off <<= 1) {
                n0 += __shfl_xor_sync(0xffffffffu, n0, off);
                g0 += __shfl_xor_sync(0xffffffffu, g0, off);
                n1 += __shfl_xor_sync(0xffffffffu, n1, off);
                g1 += __shfl_xor_sync(0xffffffffu, g1, off);
            }
            if (tq == 0) {
                if (r0 < posCnt) { atomicAdd(&g_acc[img][r0][0], n0); atomicAdd(&g_acc[img][r0][1], g0); }
                if (r1 < posCnt) { atomicAdd(&g_acc[img][r1][0], n1); atomicAdd(&g_acc[img][r1][1], g1); }
            }
        }
    }
}

// ---------------- stage 5: per-image reduction + final (ticketed) -----------
__global__ void k_redfinal(float* out) {
    int img = blockIdx.x;
    int tid = threadIdx.x;
    int posCnt = min(g_cnt[img][0], PCAP);
    int negCnt = min(g_cnt[img][1], NCAP);
    float sum = 0.f, cnt = 0.f;
    for (int a = tid; a < posCnt; a += 256) {
        float num = g_acc[img][a][0];
        float neg = g_acc[img][a][1];
        if (num > 0.f) { sum += log1pf(neg / num); cnt += 1.f; }
    }
    __shared__ float ss[256], sc[256];
    ss[tid] = sum; sc[tid] = cnt;
    __syncthreads();
    for (int o = 128; o > 0; o >>= 1) {
        if (tid < o) { ss[tid] += ss[tid + o]; sc[tid] += sc[tid + o]; }
        __syncthreads();
    }
    if (tid == 0) {
        g_imgLoss[img]  = ss[0] / fmaxf(sc[0], 1.f);
        g_imgValid[img] = (posCnt >= 2 && negCnt > 0 && sc[0] > 0.f) ? 1 : 0;
        __threadfence();
        int ticket = atomicAdd(&g_done, 1);
        if (ticket == NB - 1) {
            float v0 = g_imgValid[0] ? 1.f : 0.f;
            float v1 = g_imgValid[1] ? 1.f : 0.f;
            float s = g_imgLoss[0]*v0 + g_imgLoss[1]*v1;
            float tot = s / fmaxf(v0 + v1, 1.f);
            out[0] = (v0 + v1 > 0.f) ? tot : 0.f;
        }
    }
}

// ---------------- launch ----------------
extern "C" void kernel_launch(void* const* d_in, const int* in_sizes, int n_in,
                              void* d_out, int out_size) {
    const float* feats = (const float*)d_in[0];
    const int*   lab   = (const int*)d_in[1];
    (void)in_sizes; (void)n_in; (void)out_size;

    k_pack  <<<NROWS/8, 256>>>(lab);
    k_dild  <<<NB*4*16, 256>>>();
    k_gather<<<NB*COLCAP*4/256, 256>>>(feats);
    k_mma   <<<dim3(NXCH, NYCH, NB), 256>>>();
    k_redfinal<<<NB, 256>>>((float*)d_out);
}